// round 4
// baseline (speedup 1.0000x reference)
#include <cuda_runtime.h>
#include <cstdint>

#define NEG_INF __int_as_float(0xff800000)

static __device__ __forceinline__ float max5(float a, float b, float c, float d, float e) {
    return fmaxf(fmaxf(a, fmaxf(b, c)), fmaxf(d, e));
}

// Hex maxpool, SIZE=2, STRIDE=1, plane = 256x256 fp32.
//   even w: col w rows [h-2,h+2]; cols w+-1 rows [h-2,h+1]; cols w+-2 rows [h-1,h+1]
//   odd  w: col w rows [h-2,h+2]; cols w+-1 rows [h-1,h+2]; cols w+-2 rows [h-1,h+1]
//
// One warp per 256-wide strip of 64 rows; lane owns 8 columns.
// cp.async pipeline: 8-row smem ring per warp, prefetch distance +10
// => 7 rows (7KB) in flight per warp. 128-thread CTAs, 5 CTAs/SM
// => 20 warps/SM, ~140KB of DRAM requests in flight per SM.
__global__ __launch_bounds__(128, 5)
void hexpool_kernel(const float* __restrict__ x, float* __restrict__ y) {
    __shared__ float ring[4][8][256];   // 32KB: warp-private 8-row rings

    const int wid  = threadIdx.x >> 5;
    const int lane = threadIdx.x & 31;
    const int warp_global = blockIdx.x * 4 + wid;
    const int img   = warp_global >> 2;   // 1024 planes (N*C)
    const int chunk = warp_global & 3;    // 4 chunks of 64 rows
    const int h0    = chunk * 64;

    const float* __restrict__ in  = x + (size_t)img * 65536 + lane * 8;
    float*       __restrict__ out = y + (size_t)img * 65536 + lane * 8;
    float* wring = &ring[wid][0][0];

    // slot for local row m is (m+2) & 7
    float win[8][8];

    // Direct LDG for the prologue window rows (-2..2)
    auto load_row_g = [&](int m, float* dst) {
        const int g = h0 + m;
        if ((unsigned)g < 256u) {
            const float4 a = *reinterpret_cast<const float4*>(in + g * 256);
            const float4 b = *reinterpret_cast<const float4*>(in + g * 256 + 4);
            dst[0] = a.x; dst[1] = a.y; dst[2] = a.z; dst[3] = a.w;
            dst[4] = b.x; dst[5] = b.y; dst[6] = b.z; dst[7] = b.w;
        } else {
            #pragma unroll
            for (int j = 0; j < 8; ++j) dst[j] = NEG_INF;
        }
    };

    // Prefetch local row r into ring slot r%8. ALWAYS commits exactly one
    // group (possibly empty) so wait_group counting stays uniform.
    auto prefetch = [&](int r) {
        if (r <= 65) {
            float* s = wring + (r & 7) * 256 + lane * 8;
            const int g = h0 + r;
            if ((unsigned)g < 256u) {
                const float* gp = in + (size_t)g * 256;
                uint32_t sa = (uint32_t)__cvta_generic_to_shared(s);
                asm volatile(
                    "cp.async.cg.shared.global [%0], [%1], 16;\n\t"
                    "cp.async.cg.shared.global [%2], [%3], 16;\n\t"
                    :: "r"(sa), "l"(gp), "r"(sa + 16), "l"(gp + 4));
            } else {
                const float4 ninf = make_float4(NEG_INF, NEG_INF, NEG_INF, NEG_INF);
                *reinterpret_cast<float4*>(s)     = ninf;
                *reinterpret_cast<float4*>(s + 4) = ninf;
            }
        }
        asm volatile("cp.async.commit_group;");
    };

    auto lds_row = [&](int r, float* dst) {
        const float* s = wring + (r & 7) * 256 + lane * 8;
        const float4 a = *reinterpret_cast<const float4*>(s);
        const float4 b = *reinterpret_cast<const float4*>(s + 4);
        dst[0] = a.x; dst[1] = a.y; dst[2] = a.z; dst[3] = a.w;
        dst[4] = b.x; dst[5] = b.y; dst[6] = b.z; dst[7] = b.w;
    };

    // Prologue: rows -2..2 to registers, rows 3..9 launched into the ring
    // (7 groups pending at loop entry).
    #pragma unroll
    for (int m = -2; m <= 2; ++m) load_row_g(m, win[(m + 2) & 7]);
    #pragma unroll
    for (int r = 3; r <= 9; ++r) prefetch(r);

    for (int hh = 0; hh < 64; hh += 8) {
        #pragma unroll
        for (int u = 0; u < 8; ++u) {
            const int l = hh + u;

            // Keep the async pipe 7 rows deep (rows l+4..l+10 pending),
            // then pull row l+3 into regs (consumed next iteration).
            prefetch(l + 10);
            asm volatile("cp.async.wait_group 7;");
            if (l < 63) lds_row(l + 3, win[(u + 5) & 7]);

            // hh % 8 == 0, so slot of row (l+k) = (u + k + 2) & 7 (compile-time)
            const int s0 = (u + 0) & 7;  // row l-2
            const int s1 = (u + 1) & 7;  // row l-1
            const int sc = (u + 2) & 7;  // row l
            const int s3 = (u + 3) & 7;  // row l+1
            const int s4 = (u + 4) & 7;  // row l+2

            float m3[8], A[8], m5v[8];
            #pragma unroll
            for (int j = 0; j < 8; ++j)
                m3[j] = fmaxf(fmaxf(win[s1][j], win[sc][j]), win[s3][j]);

            // parity of global col = j&1.
            //   odd  w: A = rows [h-2,h+1] = max(m3, r_{l-2})
            //   even w: A = rows [h-1,h+2] = max(m3, r_{l+2})
            //   m5 = 5-row max = max(A, remaining row)
            #pragma unroll
            for (int j = 0; j < 8; ++j) {
                if (j & 1) { A[j]   = fmaxf(m3[j], win[s0][j]);
                             m5v[j] = fmaxf(A[j], win[s4][j]); }
                else       { A[j]   = fmaxf(m3[j], win[s4][j]);
                             m5v[j] = fmaxf(A[j], win[s0][j]); }
            }

            // Horizontal halo across lanes
            float A_l   = __shfl_up_sync(0xffffffffu, A[7], 1);
            float m3_l2 = __shfl_up_sync(0xffffffffu, m3[6], 1);
            float m3_l1 = __shfl_up_sync(0xffffffffu, m3[7], 1);
            float A_r   = __shfl_down_sync(0xffffffffu, A[0], 1);
            float m3_r1 = __shfl_down_sync(0xffffffffu, m3[0], 1);
            float m3_r2 = __shfl_down_sync(0xffffffffu, m3[1], 1);
            if (lane == 0)  { A_l = NEG_INF; m3_l1 = NEG_INF; m3_l2 = NEG_INF; }
            if (lane == 31) { A_r = NEG_INF; m3_r1 = NEG_INF; m3_r2 = NEG_INF; }

            float4 v0, v1;
            v0.x = max5(m5v[0], A_l,  A[1], m3_l2, m3[2]);
            v0.y = max5(m5v[1], A[0], A[2], m3_l1, m3[3]);
            v0.z = max5(m5v[2], A[1], A[3], m3[0], m3[4]);
            v0.w = max5(m5v[3], A[2], A[4], m3[1], m3[5]);
            v1.x = max5(m5v[4], A[3], A[5], m3[2], m3[6]);
            v1.y = max5(m5v[5], A[4], A[6], m3[3], m3[7]);
            v1.z = max5(m5v[6], A[5], A[7], m3[4], m3_r1);
            v1.w = max5(m5v[7], A[6], A_r,  m3[5], m3_r2);

            // Output never re-read: evict-first keeps L2 for the row halo.
            __stcs(reinterpret_cast<float4*>(out + (h0 + l) * 256),     v0);
            __stcs(reinterpret_cast<float4*>(out + (h0 + l) * 256 + 4), v1);
        }
    }
}

extern "C" void kernel_launch(void* const* d_in, const int* in_sizes, int n_in,
                              void* d_out, int out_size) {
    const float* x = (const float*)d_in[0];
    float*       y = (float*)d_out;
    // 1024 planes * 4 chunks = 4096 warps; 4 warps/block -> 1024 blocks
    hexpool_kernel<<<1024, 128>>>(x, y);
}

// round 5
// speedup vs baseline: 1.0658x; 1.0658x over previous
#include <cuda_runtime.h>
#include <cstdint>

#define NEG_INF __int_as_float(0xff800000)

static __device__ __forceinline__ float max5(float a, float b, float c, float d, float e) {
    return fmaxf(fmaxf(a, fmaxf(b, c)), fmaxf(d, e));
}

// Hex maxpool, SIZE=2, STRIDE=1, plane = 256x256 fp32.
//   even w: col w rows [h-2,h+2]; cols w+-1 rows [h-2,h+1]; cols w+-2 rows [h-1,h+1]
//   odd  w: col w rows [h-2,h+2]; cols w+-1 rows [h-1,h+2]; cols w+-2 rows [h-1,h+1]
//
// One warp per 256-wide strip of 64 rows; lane owns 8 columns.
// cp.async pipeline: 8-row smem ring per warp, prefetch distance +10 (7 rows
// in flight). Register window cut to a 6-slot mod-6 ring (48 regs) so the
// kernel fits 6 CTAs/SM (24 warps/SM) — occupancy, not MLP, is the R4 limiter.
__global__ __launch_bounds__(128, 6)
void hexpool_kernel(const float* __restrict__ x, float* __restrict__ y) {
    __shared__ float ring[4][8][256];   // 32KB: warp-private 8-row smem rings

    const int wid  = threadIdx.x >> 5;
    const int lane = threadIdx.x & 31;
    const int warp_global = blockIdx.x * 4 + wid;
    const int img   = warp_global >> 2;   // 1024 planes (N*C)
    const int chunk = warp_global & 3;    // 4 chunks of 64 rows
    const int h0    = chunk * 64;

    const float* __restrict__ in  = x + (size_t)img * 65536 + lane * 8;
    float*       __restrict__ out = y + (size_t)img * 65536 + lane * 8;
    float* wring = &ring[wid][0][0];

    // Register ring: local row m lives in slot (m+2) % 6. Only 6 rows are
    // ever live: l-2..l+2 plus the incoming row l+3.
    float win[6][8];

    // Direct LDG for the prologue window rows (-2..2)
    auto load_row_g = [&](int m, float* dst) {
        const int g = h0 + m;
        if ((unsigned)g < 256u) {
            const float4 a = *reinterpret_cast<const float4*>(in + g * 256);
            const float4 b = *reinterpret_cast<const float4*>(in + g * 256 + 4);
            dst[0] = a.x; dst[1] = a.y; dst[2] = a.z; dst[3] = a.w;
            dst[4] = b.x; dst[5] = b.y; dst[6] = b.z; dst[7] = b.w;
        } else {
            #pragma unroll
            for (int j = 0; j < 8; ++j) dst[j] = NEG_INF;
        }
    };

    // Prefetch local row r into smem ring slot r&7. ALWAYS commits exactly
    // one group (possibly empty) so wait_group counting stays uniform.
    auto prefetch = [&](int r) {
        if (r <= 65) {
            float* s = wring + (r & 7) * 256 + lane * 8;
            const int g = h0 + r;
            if ((unsigned)g < 256u) {
                const float* gp = in + (size_t)g * 256;
                uint32_t sa = (uint32_t)__cvta_generic_to_shared(s);
                asm volatile(
                    "cp.async.cg.shared.global [%0], [%1], 16;\n\t"
                    "cp.async.cg.shared.global [%2], [%3], 16;\n\t"
                    :: "r"(sa), "l"(gp), "r"(sa + 16), "l"(gp + 4));
            } else {
                const float4 ninf = make_float4(NEG_INF, NEG_INF, NEG_INF, NEG_INF);
                *reinterpret_cast<float4*>(s)     = ninf;
                *reinterpret_cast<float4*>(s + 4) = ninf;
            }
        }
        asm volatile("cp.async.commit_group;");
    };

    auto lds_row = [&](int r, float* dst) {
        const float* s = wring + (r & 7) * 256 + lane * 8;
        const float4 a = *reinterpret_cast<const float4*>(s);
        const float4 b = *reinterpret_cast<const float4*>(s + 4);
        dst[0] = a.x; dst[1] = a.y; dst[2] = a.z; dst[3] = a.w;
        dst[4] = b.x; dst[5] = b.y; dst[6] = b.z; dst[7] = b.w;
    };

    // Prologue: rows -2..2 -> register slots 0..4; rows 3..9 launched into
    // the smem ring (7 groups pending at loop entry).
    #pragma unroll
    for (int m = -2; m <= 2; ++m) load_row_g(m, win[m + 2]);
    #pragma unroll
    for (int r = 3; r <= 9; ++r) prefetch(r);

    // 64 rows = 11 blocks of 6 (last block partial, guarded by l < 64).
    for (int hh = 0; hh < 66; hh += 6) {
        #pragma unroll
        for (int u = 0; u < 6; ++u) {
            const int l = hh + u;
            if (l < 64) {
                // Keep the async pipe 7 rows deep (rows l+4..l+10 pending),
                // then pull row l+3 into regs (consumed next iteration).
                prefetch(l + 10);
                asm volatile("cp.async.wait_group 7;");
                // reg slot of row (l+k) = (u + k + 2) % 6 since hh % 6 == 0
                if (l < 63) lds_row(l + 3, win[(u + 5) % 6]);

                const int s0 = (u + 0) % 6;  // row l-2
                const int s1 = (u + 1) % 6;  // row l-1
                const int sc = (u + 2) % 6;  // row l
                const int s3 = (u + 3) % 6;  // row l+1
                const int s4 = (u + 4) % 6;  // row l+2

                float m3[8], A[8], m5v[8];
                #pragma unroll
                for (int j = 0; j < 8; ++j)
                    m3[j] = fmaxf(fmaxf(win[s1][j], win[sc][j]), win[s3][j]);

                // parity of global col = j&1.
                //   odd  w: A = rows [h-2,h+1] = max(m3, r_{l-2})
                //   even w: A = rows [h-1,h+2] = max(m3, r_{l+2})
                //   m5 = 5-row max = max(A, remaining row)
                #pragma unroll
                for (int j = 0; j < 8; ++j) {
                    if (j & 1) { A[j]   = fmaxf(m3[j], win[s0][j]);
                                 m5v[j] = fmaxf(A[j], win[s4][j]); }
                    else       { A[j]   = fmaxf(m3[j], win[s4][j]);
                                 m5v[j] = fmaxf(A[j], win[s0][j]); }
                }

                // Horizontal halo across lanes
                float A_l   = __shfl_up_sync(0xffffffffu, A[7], 1);
                float m3_l2 = __shfl_up_sync(0xffffffffu, m3[6], 1);
                float m3_l1 = __shfl_up_sync(0xffffffffu, m3[7], 1);
                float A_r   = __shfl_down_sync(0xffffffffu, A[0], 1);
                float m3_r1 = __shfl_down_sync(0xffffffffu, m3[0], 1);
                float m3_r2 = __shfl_down_sync(0xffffffffu, m3[1], 1);
                if (lane == 0)  { A_l = NEG_INF; m3_l1 = NEG_INF; m3_l2 = NEG_INF; }
                if (lane == 31) { A_r = NEG_INF; m3_r1 = NEG_INF; m3_r2 = NEG_INF; }

                float4 v0, v1;
                v0.x = max5(m5v[0], A_l,  A[1], m3_l2, m3[2]);
                v0.y = max5(m5v[1], A[0], A[2], m3_l1, m3[3]);
                v0.z = max5(m5v[2], A[1], A[3], m3[0], m3[4]);
                v0.w = max5(m5v[3], A[2], A[4], m3[1], m3[5]);
                v1.x = max5(m5v[4], A[3], A[5], m3[2], m3[6]);
                v1.y = max5(m5v[5], A[4], A[6], m3[3], m3[7]);
                v1.z = max5(m5v[6], A[5], A[7], m3[4], m3_r1);
                v1.w = max5(m5v[7], A[6], A_r,  m3[5], m3_r2);

                // Output never re-read: evict-first keeps L2 for the row halo.
                __stcs(reinterpret_cast<float4*>(out + (h0 + l) * 256),     v0);
                __stcs(reinterpret_cast<float4*>(out + (h0 + l) * 256 + 4), v1);
            }
        }
    }
}

extern "C" void kernel_launch(void* const* d_in, const int* in_sizes, int n_in,
                              void* d_out, int out_size) {
    const float* x = (const float*)d_in[0];
    float*       y = (float*)d_out;
    // 1024 planes * 4 chunks = 4096 warps; 4 warps/block -> 1024 blocks
    hexpool_kernel<<<1024, 128>>>(x, y);
}

// round 6
// speedup vs baseline: 1.1096x; 1.0411x over previous
#include <cuda_runtime.h>
#include <cstdint>

#define NEG_INF __int_as_float(0xff800000)

static __device__ __forceinline__ float max5(float a, float b, float c, float d, float e) {
    return fmaxf(fmaxf(a, fmaxf(b, c)), fmaxf(d, e));
}

// Hex maxpool, SIZE=2, STRIDE=1, plane = 256x256 fp32.
//   even w: col w rows [h-2,h+2]; cols w+-1 rows [h-2,h+1]; cols w+-2 rows [h-1,h+1]
//   odd  w: col w rows [h-2,h+2]; cols w+-1 rows [h-1,h+2]; cols w+-2 rows [h-1,h+1]
//
// One warp per 256-wide strip of 64 rows; lane owns 8 columns.
// Reads:  cp.async (LDGSTS) into a 6-row smem ring, 5 rows in flight.
// Writes: computed rows STS'd into a double-buffered 4-row smem stage;
//         every 4 rows one lane fires a 4KB cp.async.bulk (TMA) store.
//         -> DRAM sees long same-direction write bursts; warps never hold
//            store data or wait on store completion.
__global__ __launch_bounds__(128, 4)
void hexpool_kernel(const float* __restrict__ x, float* __restrict__ y) {
    __shared__ float inring[4][6][256];              // 24KB input rings
    __shared__ __align__(16) float ostage[4][2][4][256];  // 32KB store staging

    const int wid  = threadIdx.x >> 5;
    const int lane = threadIdx.x & 31;
    const int warp_global = blockIdx.x * 4 + wid;
    const int img   = warp_global >> 2;   // 1024 planes (N*C)
    const int chunk = warp_global & 3;    // 4 chunks of 64 rows
    const int h0    = chunk * 64;

    const float* __restrict__ in = x + (size_t)img * 65536 + lane * 8;
    float* __restrict__ outbase  = y + (size_t)img * 65536;
    float* wring = &inring[wid][0][0];

    // Register window: row m in slot (m+2)&7 (8 slots, compile-time idx).
    float win[8][8];

    auto load_row_g = [&](int m, float* dst) {
        const int g = h0 + m;
        if ((unsigned)g < 256u) {
            const float4 a = *reinterpret_cast<const float4*>(in + g * 256);
            const float4 b = *reinterpret_cast<const float4*>(in + g * 256 + 4);
            dst[0] = a.x; dst[1] = a.y; dst[2] = a.z; dst[3] = a.w;
            dst[4] = b.x; dst[5] = b.y; dst[6] = b.z; dst[7] = b.w;
        } else {
            #pragma unroll
            for (int j = 0; j < 8; ++j) dst[j] = NEG_INF;
        }
    };

    // Prefetch local row r into ring slot r%6. ALWAYS commits exactly one
    // group (possibly empty) so wait_group counting stays uniform.
    auto prefetch = [&](int r) {
        if (r <= 65) {
            float* s = wring + (r % 6) * 256 + lane * 8;
            const int g = h0 + r;
            if ((unsigned)g < 256u) {
                const float* gp = in + (size_t)g * 256;
                uint32_t sa = (uint32_t)__cvta_generic_to_shared(s);
                asm volatile(
                    "cp.async.cg.shared.global [%0], [%1], 16;\n\t"
                    "cp.async.cg.shared.global [%2], [%3], 16;\n\t"
                    :: "r"(sa), "l"(gp), "r"(sa + 16), "l"(gp + 4));
            } else {
                const float4 ninf = make_float4(NEG_INF, NEG_INF, NEG_INF, NEG_INF);
                *reinterpret_cast<float4*>(s)     = ninf;
                *reinterpret_cast<float4*>(s + 4) = ninf;
            }
        }
        asm volatile("cp.async.commit_group;");
    };

    auto lds_row = [&](int r, float* dst) {
        const float* s = wring + (r % 6) * 256 + lane * 8;
        const float4 a = *reinterpret_cast<const float4*>(s);
        const float4 b = *reinterpret_cast<const float4*>(s + 4);
        dst[0] = a.x; dst[1] = a.y; dst[2] = a.z; dst[3] = a.w;
        dst[4] = b.x; dst[5] = b.y; dst[6] = b.z; dst[7] = b.w;
    };

    // Prologue: rows -2..2 -> registers; rows 3..7 launched into the ring.
    #pragma unroll
    for (int m = -2; m <= 2; ++m) load_row_g(m, win[(m + 2) & 7]);
    #pragma unroll
    for (int r = 3; r <= 7; ++r) prefetch(r);

    for (int hh = 0; hh < 64; hh += 8) {
        #pragma unroll
        for (int u = 0; u < 8; ++u) {
            const int l = hh + u;

            if ((u & 3) == 0) {
                // About to refill the staging buffer whose bulk store was
                // issued 2 groups ago: allow at most 1 pending bulk group.
                asm volatile("cp.async.bulk.wait_group 1;");
            }

            // Input pipe: keep rows l+4..l+8 pending, pull row l+3 to regs.
            prefetch(l + 8);
            asm volatile("cp.async.wait_group 5;");
            if (l < 63) lds_row(l + 3, win[(u + 5) & 7]);

            const int s0 = (u + 0) & 7;  // row l-2
            const int s1 = (u + 1) & 7;  // row l-1
            const int sc = (u + 2) & 7;  // row l
            const int s3 = (u + 3) & 7;  // row l+1
            const int s4 = (u + 4) & 7;  // row l+2

            float m3[8], A[8], m5v[8];
            #pragma unroll
            for (int j = 0; j < 8; ++j)
                m3[j] = fmaxf(fmaxf(win[s1][j], win[sc][j]), win[s3][j]);

            // parity of global col = j&1.
            //   odd  w: A = rows [h-2,h+1] = max(m3, r_{l-2})
            //   even w: A = rows [h-1,h+2] = max(m3, r_{l+2})
            //   m5 = 5-row max = max(A, remaining row)
            #pragma unroll
            for (int j = 0; j < 8; ++j) {
                if (j & 1) { A[j]   = fmaxf(m3[j], win[s0][j]);
                             m5v[j] = fmaxf(A[j], win[s4][j]); }
                else       { A[j]   = fmaxf(m3[j], win[s4][j]);
                             m5v[j] = fmaxf(A[j], win[s0][j]); }
            }

            // Horizontal halo across lanes
            float A_l   = __shfl_up_sync(0xffffffffu, A[7], 1);
            float m3_l2 = __shfl_up_sync(0xffffffffu, m3[6], 1);
            float m3_l1 = __shfl_up_sync(0xffffffffu, m3[7], 1);
            float A_r   = __shfl_down_sync(0xffffffffu, A[0], 1);
            float m3_r1 = __shfl_down_sync(0xffffffffu, m3[0], 1);
            float m3_r2 = __shfl_down_sync(0xffffffffu, m3[1], 1);
            if (lane == 0)  { A_l = NEG_INF; m3_l1 = NEG_INF; m3_l2 = NEG_INF; }
            if (lane == 31) { A_r = NEG_INF; m3_r1 = NEG_INF; m3_r2 = NEG_INF; }

            float4 v0, v1;
            v0.x = max5(m5v[0], A_l,  A[1], m3_l2, m3[2]);
            v0.y = max5(m5v[1], A[0], A[2], m3_l1, m3[3]);
            v0.z = max5(m5v[2], A[1], A[3], m3[0], m3[4]);
            v0.w = max5(m5v[3], A[2], A[4], m3[1], m3[5]);
            v1.x = max5(m5v[4], A[3], A[5], m3[2], m3[6]);
            v1.y = max5(m5v[5], A[4], A[6], m3[3], m3[7]);
            v1.z = max5(m5v[6], A[5], A[7], m3[4], m3_r1);
            v1.w = max5(m5v[7], A[6], A_r,  m3[5], m3_r2);

            // Stage the row in smem; buf = (l>>2)&1.
            float* st = &ostage[wid][(l >> 2) & 1][l & 3][lane * 8];
            *reinterpret_cast<float4*>(st)     = v0;
            *reinterpret_cast<float4*>(st + 4) = v1;

            if ((u & 3) == 3) {
                // 4 rows (l-3..l) staged -> one 4KB bulk store burst.
                __syncwarp();
                if (lane == 0) {
                    asm volatile("fence.proxy.async.shared::cta;");
                    uint32_t src = (uint32_t)__cvta_generic_to_shared(
                        &ostage[wid][(l >> 2) & 1][0][0]);
                    float* dst = outbase + (h0 + l - 3) * 256;
                    asm volatile(
                        "cp.async.bulk.global.shared::cta.bulk_group [%0], [%1], 4096;"
                        :: "l"(dst), "r"(src) : "memory");
                    asm volatile("cp.async.bulk.commit_group;");
                }
            }
        }
    }
    // Drain outstanding bulk stores before the staging smem dies with the CTA.
    asm volatile("cp.async.bulk.wait_group 0;");
}

extern "C" void kernel_launch(void* const* d_in, const int* in_sizes, int n_in,
                              void* d_out, int out_size) {
    const float* x = (const float*)d_in[0];
    float*       y = (float*)d_out;
    // 1024 planes * 4 chunks = 4096 warps; 4 warps/block -> 1024 blocks
    hexpool_kernel<<<1024, 128>>>(x, y);
}